// round 10
// baseline (speedup 1.0000x reference)
#include <cuda_runtime.h>

// L1Distance, mixed-path + packed accumulation:
//   min path (12/16 accs):  acc2 += {min(a,b0),min(a,b1)}   (FMNMX alu + 0.5 FADD2 fma)
//       out = max(rsA + rsB - 2*acc, 0)
//   direct path (4/16 accs): acc += |a-b|                    (2 FADD, fma)
//       out = max(acc, 0)
// p=0.75 min balances alu busy (0.75*2=1.5 cyc/pair) vs fma (0.875*2=1.75).
// Geometry from R9: 64x64 tiles, whole D staged once, 4 CTAs/SM, 1024 CTAs.

constexpr int D  = 64;
constexpr int TM = 64;
constexpr int TN = 64;
constexpr int SA = 68;   // padded stride (floats)

__device__ __forceinline__ void acc2(unsigned long long& acc, float lo, float hi) {
    unsigned long long t;
    asm("mov.b64 %0, {%1, %2};" : "=l"(t) : "f"(lo), "f"(hi));
    asm("add.rn.f32x2 %0, %0, %1;" : "+l"(acc) : "l"(t));
}

__global__ __launch_bounds__(256, 4)
void l1dist_kernel(const float* __restrict__ x1, const float* __restrict__ x2,
                   float* __restrict__ out, int N2) {
    __shared__ __align__(16) float As[D * SA];  // As[d][row] = x1[i0+row][d]
    __shared__ __align__(16) float Bs[D * SA];  // Bs[d][row] = x2[j0+row][d]
    __shared__ float rsAs[TM];
    __shared__ float rsBs[TN];

    const int i0  = blockIdx.y * TM;
    const int j0  = blockIdx.x * TN;
    const int tid = (int)threadIdx.x;
    const int ty  = tid >> 4;   // 0..15 -> rows ty*4..ty*4+3
    const int tx  = tid & 15;   // 0..15 -> cols tx*4..tx*4+3

    // ---- stage both tiles transposed: 64 rows x 64 d = 1024 float4 each ----
#pragma unroll
    for (int k = 0; k < 4; k++) {
        int idx = tid + k * 256;        // 0..1023
        int row = idx >> 4;             // 0..63
        int d4  = (idx & 15) << 2;      // 0,4,...,60
        float4 a = *(const float4*)(x1 + (size_t)(i0 + row) * D + d4);
        As[(d4 + 0) * SA + row] = a.x;
        As[(d4 + 1) * SA + row] = a.y;
        As[(d4 + 2) * SA + row] = a.z;
        As[(d4 + 3) * SA + row] = a.w;
        float4 b = *(const float4*)(x2 + (size_t)(j0 + row) * D + d4);
        Bs[(d4 + 0) * SA + row] = b.x;
        Bs[(d4 + 1) * SA + row] = b.y;
        Bs[(d4 + 2) * SA + row] = b.z;
        Bs[(d4 + 3) * SA + row] = b.w;
    }
    __syncthreads();

    // ---- in-block rowsums from staged tiles (threads 0..127) ----
    if (tid < TM + TN) {
        const float* col = (tid < TM) ? &As[tid] : &Bs[tid - TM];
        float s = 0.f;
#pragma unroll
        for (int d = 0; d < D; d++) s += col[d * SA];
        if (tid < TM) rsAs[tid] = s;
        else          rsBs[tid - TM] = s;
    }

    // ---- main compute ----
    // rows m=0..2: min path, packed accs accp[m][p] for col pairs (2p, 2p+1)
    // row  m=3   : direct path, scalar accs accd[n]
    unsigned long long accp[3][2];
#pragma unroll
    for (int m = 0; m < 3; m++) { accp[m][0] = 0ULL; accp[m][1] = 0ULL; }
    float accd[4] = {0.f, 0.f, 0.f, 0.f};

#pragma unroll 16
    for (int d = 0; d < D; d++) {
        float4 av = *(const float4*)(&As[d * SA] + ty * 4);
        float4 bv = *(const float4*)(&Bs[d * SA] + tx * 4);
        float ra[4] = {av.x, av.y, av.z, av.w};
#pragma unroll
        for (int m = 0; m < 3; m++) {
            acc2(accp[m][0], fminf(ra[m], bv.x), fminf(ra[m], bv.y));
            acc2(accp[m][1], fminf(ra[m], bv.z), fminf(ra[m], bv.w));
        }
        accd[0] += fabsf(ra[3] - bv.x);
        accd[1] += fabsf(ra[3] - bv.y);
        accd[2] += fabsf(ra[3] - bv.z);
        accd[3] += fabsf(ra[3] - bv.w);
    }
    __syncthreads();   // rowsum writes -> epilogue reads

    // ---- epilogue ----
    float rsb[4] = {rsBs[tx * 4 + 0], rsBs[tx * 4 + 1],
                    rsBs[tx * 4 + 2], rsBs[tx * 4 + 3]};
#pragma unroll
    for (int m = 0; m < 3; m++) {
        float rsa = rsAs[ty * 4 + m];
        int r = i0 + ty * 4 + m;
        float* orow = out + (size_t)r * N2 + j0 + tx * 4;
        float2 p0 = *(float2*)&accp[m][0];
        float2 p1 = *(float2*)&accp[m][1];
        float v0 = fmaxf(fmaf(-2.f, p0.x, rsa + rsb[0]), 0.f);
        float v1 = fmaxf(fmaf(-2.f, p0.y, rsa + rsb[1]), 0.f);
        float v2 = fmaxf(fmaf(-2.f, p1.x, rsa + rsb[2]), 0.f);
        float v3 = fmaxf(fmaf(-2.f, p1.y, rsa + rsb[3]), 0.f);
        *(float4*)orow = make_float4(v0, v1, v2, v3);
    }
    {
        int r = i0 + ty * 4 + 3;
        float* orow = out + (size_t)r * N2 + j0 + tx * 4;
        *(float4*)orow = make_float4(fmaxf(accd[0], 0.f), fmaxf(accd[1], 0.f),
                                     fmaxf(accd[2], 0.f), fmaxf(accd[3], 0.f));
    }
}

extern "C" void kernel_launch(void* const* d_in, const int* in_sizes, int n_in,
                              void* d_out, int out_size) {
    const float* x1 = (const float*)d_in[0];
    const float* x2 = (const float*)d_in[1];
    float* out = (float*)d_out;

    int N1 = in_sizes[0] / D;   // 2048
    int N2 = in_sizes[1] / D;   // 2048

    dim3 grid(N2 / TN, N1 / TM);   // 32 x 32 = 1024 blocks
    l1dist_kernel<<<grid, 256>>>(x1, x2, out, N2);
}

// round 11
// speedup vs baseline: 1.2797x; 1.2797x over previous
#include <cuda_runtime.h>

// L1Distance, three-binder attack:
//   rows 0-5 per thread (min path, packed):  acc2 += {min(a,b0),min(a,b1)}
//        out = max(rsA + rsB - 2*acc, 0)      [FMNMX alu + 0.5 FADD2 fma /pair]
//   rows 6-7 per thread (direct path):        acc += |a-b|; out = max(acc,0)
//        [2 FADD fma /pair]
// 128x128 tile, R1's conflict-free LDS.128 compute mapping.
// Staging: d-per-lane (lane l <-> dim d) -> coalesced LDG.32, STS.32 at bank
// stride 4 (4-way, vs 16-way before) -> staging crossbar cost /8.

constexpr int D    = 64;
constexpr int TILE = 128;
constexpr int DC   = 32;    // d staged in two chunks (smem 33.8KB)
constexpr int ST   = 132;   // padded stride (floats), 16B-aligned rows

__device__ __forceinline__ void acc2(unsigned long long& acc, float lo, float hi) {
    unsigned long long t;
    asm("mov.b64 %0, {%1, %2};" : "=l"(t) : "f"(lo), "f"(hi));
    asm("add.rn.f32x2 %0, %0, %1;" : "+l"(acc) : "l"(t));
}

__global__ __launch_bounds__(256, 2)
void l1dist_kernel(const float* __restrict__ x1, const float* __restrict__ x2,
                   float* __restrict__ out, int N2) {
    __shared__ __align__(16) float As[DC * ST];   // As[d][row] = x1[i0+row][dc+d]
    __shared__ __align__(16) float Bs[DC * ST];   // Bs[d][row] = x2[j0+row][dc+d]
    __shared__ float rsAs[TILE];
    __shared__ float rsBs[TILE];

    const int i0  = blockIdx.y * TILE;
    const int j0  = blockIdx.x * TILE;
    const int tid = (int)threadIdx.x;
    const int ty  = tid >> 4;     // 0..15
    const int tx  = tid & 15;     // 0..15
    const int w   = tid >> 5;     // warp 0..7
    const int l   = tid & 31;     // lane = dimension within chunk

    // min-path packed accs: m=0..5 (rows ty*4+{0..3}, ty*4+64+{0,1}),
    // 4 u64 each covering col pairs (tx*4+0,1)(+2,3)(+64+0,1)(+64+2,3)
    unsigned long long accp[6][4];
#pragma unroll
    for (int m = 0; m < 6; m++)
#pragma unroll
        for (int p = 0; p < 4; p++) accp[m][p] = 0ULL;
    // direct-path scalar accs: m=6,7 (rows ty*4+64+{2,3}) x 8 cols
    float accd[2][8];
#pragma unroll
    for (int m = 0; m < 2; m++)
#pragma unroll
        for (int n = 0; n < 8; n++) accd[m][n] = 0.0f;

    float rs = 0.0f;   // per-thread rowsum piece (threads 0..255)

    for (int dc = 0; dc < D; dc += DC) {
        // ---- stage d-per-lane: lane l = dim, warp covers 16 rows per tile ----
        // LDG.32: warp reads 32 consecutive floats of one row (128B coalesced).
        // STS.32: banks (4*l + row) % 32 -> 4-way conflict (was 16-way).
#pragma unroll
        for (int r8 = 0; r8 < 16; r8++) {
            int row = w * 16 + r8;
            As[l * ST + row] = x1[(size_t)(i0 + row) * D + dc + l];
            Bs[l * ST + row] = x2[(size_t)(j0 + row) * D + dc + l];
        }
        __syncthreads();

        // ---- partial rowsums from staged tiles (all 256 threads) ----
        {
            const float* col = (tid < TILE) ? &As[tid] : &Bs[tid - TILE];
#pragma unroll
            for (int d = 0; d < DC; d++) rs += col[d * ST];
        }

        // ---- compute: R1 mapping (conflict-free LDS.128) ----
#pragma unroll 2
        for (int d = 0; d < DC; d++) {
            const float* as = &As[d * ST];
            const float* bs = &Bs[d * ST];
            float4 a0 = *(const float4*)(as + ty * 4);
            float4 a1 = *(const float4*)(as + ty * 4 + 64);
            float4 b0 = *(const float4*)(bs + tx * 4);
            float4 b1 = *(const float4*)(bs + tx * 4 + 64);
            float ra[8] = {a0.x, a0.y, a0.z, a0.w, a1.x, a1.y, a1.z, a1.w};
            float rb[8] = {b0.x, b0.y, b0.z, b0.w, b1.x, b1.y, b1.z, b1.w};
#pragma unroll
            for (int m = 0; m < 6; m++) {
                acc2(accp[m][0], fminf(ra[m], rb[0]), fminf(ra[m], rb[1]));
                acc2(accp[m][1], fminf(ra[m], rb[2]), fminf(ra[m], rb[3]));
                acc2(accp[m][2], fminf(ra[m], rb[4]), fminf(ra[m], rb[5]));
                acc2(accp[m][3], fminf(ra[m], rb[6]), fminf(ra[m], rb[7]));
            }
#pragma unroll
            for (int m = 0; m < 2; m++)
#pragma unroll
                for (int n = 0; n < 8; n++)
                    accd[m][n] += fabsf(ra[6 + m] - rb[n]);
        }
        __syncthreads();
    }

    // ---- publish rowsums ----
    if (tid < TILE) rsAs[tid] = rs;
    else            rsBs[tid - TILE] = rs;
    __syncthreads();

    float rsb0[4], rsb1[4];
#pragma unroll
    for (int n = 0; n < 4; n++) {
        rsb0[n] = rsBs[tx * 4 + n];
        rsb1[n] = rsBs[tx * 4 + 64 + n];
    }

    // ---- epilogue: min-path rows (m = 0..5) ----
#pragma unroll
    for (int m = 0; m < 6; m++) {
        int rloc = (m < 4) ? (ty * 4 + m) : (ty * 4 + 64 + (m - 4));
        float rsa = rsAs[rloc];
        float* orow = out + (size_t)(i0 + rloc) * N2 + j0 + tx * 4;
        float2 p0 = *(float2*)&accp[m][0];
        float2 p1 = *(float2*)&accp[m][1];
        float2 p2 = *(float2*)&accp[m][2];
        float2 p3 = *(float2*)&accp[m][3];
        *(float4*)orow = make_float4(
            fmaxf(fmaf(-2.f, p0.x, rsa + rsb0[0]), 0.f),
            fmaxf(fmaf(-2.f, p0.y, rsa + rsb0[1]), 0.f),
            fmaxf(fmaf(-2.f, p1.x, rsa + rsb0[2]), 0.f),
            fmaxf(fmaf(-2.f, p1.y, rsa + rsb0[3]), 0.f));
        *(float4*)(orow + 64) = make_float4(
            fmaxf(fmaf(-2.f, p2.x, rsa + rsb1[0]), 0.f),
            fmaxf(fmaf(-2.f, p2.y, rsa + rsb1[1]), 0.f),
            fmaxf(fmaf(-2.f, p3.x, rsa + rsb1[2]), 0.f),
            fmaxf(fmaf(-2.f, p3.y, rsa + rsb1[3]), 0.f));
    }
    // ---- epilogue: direct-path rows (m = 6,7 -> rows ty*4+64+2, +3) ----
#pragma unroll
    for (int m = 0; m < 2; m++) {
        int rloc = ty * 4 + 64 + 2 + m;
        float* orow = out + (size_t)(i0 + rloc) * N2 + j0 + tx * 4;
        *(float4*)orow = make_float4(
            fmaxf(accd[m][0], 0.f), fmaxf(accd[m][1], 0.f),
            fmaxf(accd[m][2], 0.f), fmaxf(accd[m][3], 0.f));
        *(float4*)(orow + 64) = make_float4(
            fmaxf(accd[m][4], 0.f), fmaxf(accd[m][5], 0.f),
            fmaxf(accd[m][6], 0.f), fmaxf(accd[m][7], 0.f));
    }
}

extern "C" void kernel_launch(void* const* d_in, const int* in_sizes, int n_in,
                              void* d_out, int out_size) {
    const float* x1 = (const float*)d_in[0];
    const float* x2 = (const float*)d_in[1];
    float* out = (float*)d_out;

    int N1 = in_sizes[0] / D;   // 2048
    int N2 = in_sizes[1] / D;   // 2048

    dim3 grid(N2 / TILE, N1 / TILE);   // 16 x 16 = 256 blocks
    l1dist_kernel<<<grid, 256>>>(x1, x2, out, N2);
}

// round 12
// speedup vs baseline: 1.2895x; 1.0077x over previous
#include <cuda_runtime.h>

// L1Distance, all-binders-at-once configuration:
//  - 128x64 tile, 8x4 per thread: 3 LDS.128/d/thread = 1.5 B/pair (crossbar ~21K wf)
//  - d-per-lane staging: coalesced LDG.32, STS.32 at 4-way conflict (~3.5K wf)
//  - mixed math: 5 rows min-path packed (FMNMX alu + 0.5 FADD2 fma),
//                3 rows direct |a-b| (2 FADD fma)  -> alu 17.7K / fma 19.5K busy
//  - ~64 regs -> 4 CTAs/SM = 8 warps/SMSP (duty), 512-CTA grid = single full wave
// out[i][j]: min rows  = max(rsA+rsB-2*sum_min, 0); direct rows = max(sum_abs, 0)

constexpr int D   = 64;
constexpr int TM  = 128;
constexpr int TN  = 64;
constexpr int DC  = 32;    // two d-chunks; smem 26.4KB -> 4 CTAs/SM
constexpr int STA = 132;   // As stride (128 + 4 pad)
constexpr int STB = 68;    // Bs stride (64 + 4 pad)

__device__ __forceinline__ void acc2(unsigned long long& acc, float lo, float hi) {
    unsigned long long t;
    asm("mov.b64 %0, {%1, %2};" : "=l"(t) : "f"(lo), "f"(hi));
    asm("add.rn.f32x2 %0, %0, %1;" : "+l"(acc) : "l"(t));
}

__global__ __launch_bounds__(256, 4)
void l1dist_kernel(const float* __restrict__ x1, const float* __restrict__ x2,
                   float* __restrict__ out, int N2) {
    __shared__ __align__(16) float As[DC * STA];  // As[d][row] = x1[i0+row][dc+d]
    __shared__ __align__(16) float Bs[DC * STB];  // Bs[d][row] = x2[j0+row][dc+d]
    __shared__ float rsAs[TM];
    __shared__ float rsBs[TN];

    const int i0  = blockIdx.y * TM;
    const int j0  = blockIdx.x * TN;
    const int tid = (int)threadIdx.x;
    const int ty  = tid >> 4;     // 0..15: rows ty*4+{0..3} and 64+ty*4+{0..3}
    const int tx  = tid & 15;     // 0..15: cols tx*4+{0..3}
    const int w   = tid >> 5;     // warp 0..7
    const int l   = tid & 31;     // lane = dim within chunk

    // min-path rows m=0..4 (rows ty*4+{0..3}, 64+ty*4): packed col-pair accs
    unsigned long long accp[5][2];
#pragma unroll
    for (int m = 0; m < 5; m++) { accp[m][0] = 0ULL; accp[m][1] = 0ULL; }
    // direct-path rows m=5..7 (rows 64+ty*4+{1,2,3}): scalar accs
    float accd[3][4];
#pragma unroll
    for (int m = 0; m < 3; m++)
#pragma unroll
        for (int n = 0; n < 4; n++) accd[m][n] = 0.0f;

    float rs = 0.0f;   // per-thread rowsum piece

    for (int dc = 0; dc < D; dc += DC) {
        // ---- stage A (d-per-lane): warp w -> rows w*16..w*16+15 ----
#pragma unroll
        for (int r = 0; r < 16; r++) {
            int row = w * 16 + r;
            As[l * STA + row] = x1[(size_t)(i0 + row) * D + dc + l];
        }
        // ---- stage B: warp w -> rows w*8..w*8+7 ----
#pragma unroll
        for (int r = 0; r < 8; r++) {
            int row = w * 8 + r;
            Bs[l * STB + row] = x2[(size_t)(j0 + row) * D + dc + l];
        }
        __syncthreads();

        // ---- partial rowsums from staged tiles ----
        if (tid < TM) {
            const float* col = &As[tid];
#pragma unroll
            for (int d = 0; d < DC; d++) rs += col[d * STA];
        } else if (tid < TM + TN) {
            const float* col = &Bs[tid - TM];
#pragma unroll
            for (int d = 0; d < DC; d++) rs += col[d * STB];
        }

        // ---- compute ----
#pragma unroll 4
        for (int d = 0; d < DC; d++) {
            const float* as = &As[d * STA];
            float4 a0 = *(const float4*)(as + ty * 4);
            float4 a1 = *(const float4*)(as + ty * 4 + 64);
            float4 bv = *(const float4*)(&Bs[d * STB] + tx * 4);
            float ram[5] = {a0.x, a0.y, a0.z, a0.w, a1.x};   // min rows
            float rad[3] = {a1.y, a1.z, a1.w};               // direct rows
#pragma unroll
            for (int m = 0; m < 5; m++) {
                acc2(accp[m][0], fminf(ram[m], bv.x), fminf(ram[m], bv.y));
                acc2(accp[m][1], fminf(ram[m], bv.z), fminf(ram[m], bv.w));
            }
#pragma unroll
            for (int m = 0; m < 3; m++) {
                accd[m][0] += fabsf(rad[m] - bv.x);
                accd[m][1] += fabsf(rad[m] - bv.y);
                accd[m][2] += fabsf(rad[m] - bv.z);
                accd[m][3] += fabsf(rad[m] - bv.w);
            }
        }
        __syncthreads();
    }

    // ---- publish rowsums ----
    if (tid < TM)            rsAs[tid] = rs;
    else if (tid < TM + TN)  rsBs[tid - TM] = rs;
    __syncthreads();

    float rsb[4] = {rsBs[tx * 4 + 0], rsBs[tx * 4 + 1],
                    rsBs[tx * 4 + 2], rsBs[tx * 4 + 3]};

    // ---- epilogue: min-path rows ----
#pragma unroll
    for (int m = 0; m < 5; m++) {
        int rloc = (m < 4) ? (ty * 4 + m) : (64 + ty * 4);
        float rsa = rsAs[rloc];
        float* orow = out + (size_t)(i0 + rloc) * N2 + j0 + tx * 4;
        float2 p0 = *(float2*)&accp[m][0];
        float2 p1 = *(float2*)&accp[m][1];
        *(float4*)orow = make_float4(
            fmaxf(fmaf(-2.f, p0.x, rsa + rsb[0]), 0.f),
            fmaxf(fmaf(-2.f, p0.y, rsa + rsb[1]), 0.f),
            fmaxf(fmaf(-2.f, p1.x, rsa + rsb[2]), 0.f),
            fmaxf(fmaf(-2.f, p1.y, rsa + rsb[3]), 0.f));
    }
    // ---- epilogue: direct-path rows ----
#pragma unroll
    for (int m = 0; m < 3; m++) {
        int rloc = 64 + ty * 4 + 1 + m;
        float* orow = out + (size_t)(i0 + rloc) * N2 + j0 + tx * 4;
        *(float4*)orow = make_float4(
            fmaxf(accd[m][0], 0.f), fmaxf(accd[m][1], 0.f),
            fmaxf(accd[m][2], 0.f), fmaxf(accd[m][3], 0.f));
    }
}

extern "C" void kernel_launch(void* const* d_in, const int* in_sizes, int n_in,
                              void* d_out, int out_size) {
    const float* x1 = (const float*)d_in[0];
    const float* x2 = (const float*)d_in[1];
    float* out = (float*)d_out;

    int N1 = in_sizes[0] / D;   // 2048
    int N2 = in_sizes[1] / D;   // 2048

    dim3 grid(N2 / TN, N1 / TM);   // 32 x 16 = 512 blocks (one full wave @ 4/SM)
    l1dist_kernel<<<grid, 256>>>(x1, x2, out, N2);
}